// round 7
// baseline (speedup 1.0000x reference)
#include <cuda_runtime.h>
#include <cuda_bf16.h>
#include <math.h>

// ---------------------------------------------------------------------------
// Problem constants
// ---------------------------------------------------------------------------
#define TT   2048
#define DD   3584
#define NH   28
#define KVH  4
#define HD   128
#define GRP  7              // NH / KVH
#define KVW  (KVH*HD)       // 512
#define QW   (NH*HD)        // 3584

// ---------------------------------------------------------------------------
// Device scratch (no allocation allowed)
// ---------------------------------------------------------------------------
__device__ float g_q [TT * QW];
__device__ float g_k [TT * KVW];
__device__ float g_v [TT * KVW];
__device__ float g_ao[TT * QW];

// ---------------------------------------------------------------------------
// Classic 128x128x8 SGEMM, A[M,K] row-major, B[K,N] row-major, optional bias[N]
// 256 threads, 8x8 micro-tile per thread.
// ---------------------------------------------------------------------------
#define BM 128
#define BN 128
#define BK 8

__global__ __launch_bounds__(256, 2)
void sgemm_bias_kernel(const float* __restrict__ A, const float* __restrict__ B,
                       const float* __restrict__ bias, float* __restrict__ C,
                       int M, int N, int K)
{
    __shared__ float As[BK][BM];
    __shared__ float Bs[BK][BN];

    const int tid = threadIdx.x;
    const int tx  = tid & 15;
    const int ty  = tid >> 4;

    const float* Ab = A + (size_t)blockIdx.y * BM * K;
    const float* Bb = B + (size_t)blockIdx.x * BN;

    const int aRow = tid >> 1;
    const int aCol = (tid & 1) * 4;
    const int bRow = tid >> 5;
    const int bCol = (tid & 31) * 4;

    float acc[8][8];
    #pragma unroll
    for (int i = 0; i < 8; i++)
        #pragma unroll
        for (int j = 0; j < 8; j++) acc[i][j] = 0.f;

    for (int k0 = 0; k0 < K; k0 += BK) {
        float4 a = *(const float4*)(Ab + (size_t)aRow * K + k0 + aCol);
        As[aCol + 0][aRow] = a.x;
        As[aCol + 1][aRow] = a.y;
        As[aCol + 2][aRow] = a.z;
        As[aCol + 3][aRow] = a.w;
        *(float4*)(&Bs[bRow][bCol]) =
            *(const float4*)(Bb + (size_t)(k0 + bRow) * N + bCol);
        __syncthreads();

        #pragma unroll
        for (int kk = 0; kk < BK; kk++) {
            float ar[8], br[8];
            *(float4*)(ar)     = *(float4*)(&As[kk][ty * 8]);
            *(float4*)(ar + 4) = *(float4*)(&As[kk][ty * 8 + 4]);
            *(float4*)(br)     = *(float4*)(&Bs[kk][tx * 8]);
            *(float4*)(br + 4) = *(float4*)(&Bs[kk][tx * 8 + 4]);
            #pragma unroll
            for (int i = 0; i < 8; i++)
                #pragma unroll
                for (int j = 0; j < 8; j++)
                    acc[i][j] += ar[i] * br[j];
        }
        __syncthreads();
    }

    float bj[8];
    #pragma unroll
    for (int j = 0; j < 8; j++)
        bj[j] = bias ? bias[blockIdx.x * BN + tx * 8 + j] : 0.f;

    #pragma unroll
    for (int i = 0; i < 8; i++) {
        const size_t row = (size_t)blockIdx.y * BM + ty * 8 + i;
        float* crow = C + row * N + blockIdx.x * BN + tx * 8;
        float4 v0, v1;
        v0.x = acc[i][0] + bj[0]; v0.y = acc[i][1] + bj[1];
        v0.z = acc[i][2] + bj[2]; v0.w = acc[i][3] + bj[3];
        v1.x = acc[i][4] + bj[4]; v1.y = acc[i][5] + bj[5];
        v1.z = acc[i][6] + bj[6]; v1.w = acc[i][7] + bj[7];
        *(float4*)(crow)     = v0;
        *(float4*)(crow + 4) = v1;
    }
}

// ---------------------------------------------------------------------------
// RoPE (in-place). One thread per (t, head, pair i<64).
// ---------------------------------------------------------------------------
__global__ void rope_kernel(float* __restrict__ buf,
                            const float* __restrict__ sinT,
                            const float* __restrict__ cosT,
                            int nheads)
{
    int idx = blockIdx.x * blockDim.x + threadIdx.x;
    int total = TT * nheads * (HD / 2);
    if (idx >= total) return;
    int i = idx & 63;
    int h = (idx >> 6) % nheads;
    int t = idx / (64 * nheads);

    float* p = buf + (size_t)t * (nheads * HD) + h * HD;
    float x1 = p[i];
    float x2 = p[i + 64];
    float s = sinT[t * 64 + i];
    float c = cosT[t * 64 + i];
    p[i]      = x1 * c - x2 * s;
    p[i + 64] = x2 * c + x1 * s;
}

// ---------------------------------------------------------------------------
// Flash attention (fp32, causal, GQA). Tile 64 queries x 64 keys, H=128.
// 256 threads = 16x16; S micro-tile 4x4 per thread; O micro-tile 4x8.
// Q,K stored transposed in smem ([H][64+pad]) for conflict-free LDS.128.
// ---------------------------------------------------------------------------
#define AT_BM 64
#define AT_BN 64
#define QK_PITCH 68   // 64 + 4 pad, keeps rows 16B-aligned

#define ATT_SMEM_FLOATS (2 * HD * QK_PITCH + AT_BN * HD + AT_BM * AT_BN)

__global__ __launch_bounds__(256, 1)
void attn_kernel(const float* __restrict__ qb, const float* __restrict__ kb,
                 const float* __restrict__ vb, float* __restrict__ ob)
{
    extern __shared__ float sm[];
    float* Qst = sm;                         // [128][QK_PITCH]
    float* Kst = Qst + HD * QK_PITCH;        // [128][QK_PITCH]
    float* Vs  = Kst + HD * QK_PITCH;        // [64][128]
    float* Ps  = Vs  + AT_BN * HD;           // [64][64]

    const int tid = threadIdx.x;
    const int tx  = tid & 15;
    const int ty  = tid >> 4;
    const int qi  = blockIdx.x;          // query block
    const int n   = blockIdx.y;          // head
    const int kh  = n / GRP;
    const int q0  = qi * AT_BM;

    // load Q tile transposed
    #pragma unroll
    for (int it = 0; it < 8; it++) {
        int idx = (it * 256 + tid) * 4;
        int row = idx >> 7;
        int h   = idx & 127;
        float4 v = *(const float4*)(qb + (size_t)(q0 + row) * QW + n * HD + h);
        Qst[(h + 0) * QK_PITCH + row] = v.x;
        Qst[(h + 1) * QK_PITCH + row] = v.y;
        Qst[(h + 2) * QK_PITCH + row] = v.z;
        Qst[(h + 3) * QK_PITCH + row] = v.w;
    }

    float m_reg[4], l_reg[4], acc[4][8];
    #pragma unroll
    for (int i = 0; i < 4; i++) {
        m_reg[i] = -1e30f; l_reg[i] = 0.f;
        #pragma unroll
        for (int j = 0; j < 8; j++) acc[i][j] = 0.f;
    }

    const float scale = 0.08838834764831845f;   // 1/sqrt(128)

    for (int kbk = 0; kbk <= qi; kbk++) {
        const int k0 = kbk * AT_BN;
        __syncthreads();   // previous iteration consumers done

        // load K (transposed) and V
        #pragma unroll
        for (int it = 0; it < 8; it++) {
            int idx = (it * 256 + tid) * 4;
            int row = idx >> 7;
            int h   = idx & 127;
            float4 vk = *(const float4*)(kb + (size_t)(k0 + row) * KVW + kh * HD + h);
            Kst[(h + 0) * QK_PITCH + row] = vk.x;
            Kst[(h + 1) * QK_PITCH + row] = vk.y;
            Kst[(h + 2) * QK_PITCH + row] = vk.z;
            Kst[(h + 3) * QK_PITCH + row] = vk.w;
            float4 vv = *(const float4*)(vb + (size_t)(k0 + row) * KVW + kh * HD + h);
            *(float4*)(Vs + row * HD + h) = vv;
        }
        __syncthreads();

        // S = Q K^T  (4x4 per thread)
        float s[4][4];
        #pragma unroll
        for (int i = 0; i < 4; i++)
            #pragma unroll
            for (int j = 0; j < 4; j++) s[i][j] = 0.f;

        #pragma unroll 8
        for (int kk = 0; kk < HD; kk++) {
            float4 qr = *(float4*)(Qst + kk * QK_PITCH + ty * 4);
            float4 kr = *(float4*)(Kst + kk * QK_PITCH + tx * 4);
            s[0][0] += qr.x * kr.x; s[0][1] += qr.x * kr.y; s[0][2] += qr.x * kr.z; s[0][3] += qr.x * kr.w;
            s[1][0] += qr.y * kr.x; s[1][1] += qr.y * kr.y; s[1][2] += qr.y * kr.z; s[1][3] += qr.y * kr.w;
            s[2][0] += qr.z * kr.x; s[2][1] += qr.z * kr.y; s[2][2] += qr.z * kr.z; s[2][3] += qr.z * kr.w;
            s[3][0] += qr.w * kr.x; s[3][1] += qr.w * kr.y; s[3][2] += qr.w * kr.z; s[3][3] += qr.w * kr.w;
        }

        // scale + causal mask + online softmax update
        #pragma unroll
        for (int i = 0; i < 4; i++) {
            const int gq = q0 + ty * 4 + i;
            float rmax = -1e30f;
            #pragma unroll
            for (int j = 0; j < 4; j++) {
                int gk = k0 + tx * 4 + j;
                float sv = s[i][j] * scale;
                if (gk > gq) sv = -1e30f;
                s[i][j] = sv;
                rmax = fmaxf(rmax, sv);
            }
            // reduce max across the 16 lanes that share this row
            #pragma unroll
            for (int off = 8; off > 0; off >>= 1)
                rmax = fmaxf(rmax, __shfl_xor_sync(0xffffffffu, rmax, off));

            float m_new = fmaxf(m_reg[i], rmax);
            float alpha = __expf(m_reg[i] - m_new);

            float rsum = 0.f;
            #pragma unroll
            for (int j = 0; j < 4; j++) {
                float p = __expf(s[i][j] - m_new);
                s[i][j] = p;
                rsum += p;
            }
            #pragma unroll
            for (int off = 8; off > 0; off >>= 1)
                rsum += __shfl_xor_sync(0xffffffffu, rsum, off);

            l_reg[i] = l_reg[i] * alpha + rsum;
            m_reg[i] = m_new;

            #pragma unroll
            for (int j = 0; j < 8; j++) acc[i][j] *= alpha;

            #pragma unroll
            for (int j = 0; j < 4; j++)
                Ps[(ty * 4 + i) * AT_BN + tx * 4 + j] = s[i][j];
        }
        __syncthreads();

        // O += P @ V  (4 rows x 8 cols per thread)
        #pragma unroll 4
        for (int kk = 0; kk < AT_BN; kk++) {
            float4 v0 = *(float4*)(Vs + kk * HD + tx * 8);
            float4 v1 = *(float4*)(Vs + kk * HD + tx * 8 + 4);
            float p0 = Ps[(ty * 4 + 0) * AT_BN + kk];
            float p1 = Ps[(ty * 4 + 1) * AT_BN + kk];
            float p2 = Ps[(ty * 4 + 2) * AT_BN + kk];
            float p3 = Ps[(ty * 4 + 3) * AT_BN + kk];
            acc[0][0] += p0 * v0.x; acc[0][1] += p0 * v0.y; acc[0][2] += p0 * v0.z; acc[0][3] += p0 * v0.w;
            acc[0][4] += p0 * v1.x; acc[0][5] += p0 * v1.y; acc[0][6] += p0 * v1.z; acc[0][7] += p0 * v1.w;
            acc[1][0] += p1 * v0.x; acc[1][1] += p1 * v0.y; acc[1][2] += p1 * v0.z; acc[1][3] += p1 * v0.w;
            acc[1][4] += p1 * v1.x; acc[1][5] += p1 * v1.y; acc[1][6] += p1 * v1.z; acc[1][7] += p1 * v1.w;
            acc[2][0] += p2 * v0.x; acc[2][1] += p2 * v0.y; acc[2][2] += p2 * v0.z; acc[2][3] += p2 * v0.w;
            acc[2][4] += p2 * v1.x; acc[2][5] += p2 * v1.y; acc[2][6] += p2 * v1.z; acc[2][7] += p2 * v1.w;
            acc[3][0] += p3 * v0.x; acc[3][1] += p3 * v0.y; acc[3][2] += p3 * v0.z; acc[3][3] += p3 * v0.w;
            acc[3][4] += p3 * v1.x; acc[3][5] += p3 * v1.y; acc[3][6] += p3 * v1.z; acc[3][7] += p3 * v1.w;
        }
    }

    // epilogue: O / l
    #pragma unroll
    for (int i = 0; i < 4; i++) {
        float inv = 1.f / l_reg[i];
        const size_t row = q0 + ty * 4 + i;
        float* orow = ob + row * QW + n * HD + tx * 8;
        float4 v0, v1;
        v0.x = acc[i][0] * inv; v0.y = acc[i][1] * inv;
        v0.z = acc[i][2] * inv; v0.w = acc[i][3] * inv;
        v1.x = acc[i][4] * inv; v1.y = acc[i][5] * inv;
        v1.z = acc[i][6] * inv; v1.w = acc[i][7] * inv;
        *(float4*)(orow)     = v0;
        *(float4*)(orow + 4) = v1;
    }
}

// ---------------------------------------------------------------------------
// Launch
//   inputs: 0:x 1:attn_mask 2:sin 3:cos 4:wq 5:wk 6:wv 7:wo 8:q_bias 9:k_bias 10:v_bias
// ---------------------------------------------------------------------------
extern "C" void kernel_launch(void* const* d_in, const int* in_sizes, int n_in,
                              void* d_out, int out_size)
{
    const float* x      = (const float*)d_in[0];
    const float* sinT   = (const float*)d_in[2];
    const float* cosT   = (const float*)d_in[3];
    const float* wq     = (const float*)d_in[4];
    const float* wk     = (const float*)d_in[5];
    const float* wv     = (const float*)d_in[6];
    const float* wo     = (const float*)d_in[7];
    const float* q_bias = (const float*)d_in[8];
    const float* k_bias = (const float*)d_in[9];
    const float* v_bias = (const float*)d_in[10];
    float* out = (float*)d_out;

    float *qp, *kp, *vp, *aop;
    cudaGetSymbolAddress((void**)&qp,  g_q);
    cudaGetSymbolAddress((void**)&kp,  g_k);
    cudaGetSymbolAddress((void**)&vp,  g_v);
    cudaGetSymbolAddress((void**)&aop, g_ao);

    // QKV projections (+bias)
    {
        dim3 grid(QW / BN, TT / BM);
        sgemm_bias_kernel<<<grid, 256>>>(x, wq, q_bias, qp, TT, QW, DD);
    }
    {
        dim3 grid(KVW / BN, TT / BM);
        sgemm_bias_kernel<<<grid, 256>>>(x, wk, k_bias, kp, TT, KVW, DD);
        sgemm_bias_kernel<<<grid, 256>>>(x, wv, v_bias, vp, TT, KVW, DD);
    }

    // RoPE
    {
        int totq = TT * NH * (HD / 2);
        rope_kernel<<<(totq + 255) / 256, 256>>>(qp, sinT, cosT, NH);
        int totk = TT * KVH * (HD / 2);
        rope_kernel<<<(totk + 255) / 256, 256>>>(kp, sinT, cosT, KVH);
    }

    // Attention
    {
        const size_t smem = ATT_SMEM_FLOATS * sizeof(float);
        cudaFuncSetAttribute(attn_kernel,
                             cudaFuncAttributeMaxDynamicSharedMemorySize,
                             (int)smem);
        dim3 grid(TT / AT_BM, NH);
        attn_kernel<<<grid, 256, smem>>>(qp, kp, vp, aop);
    }

    // Output projection
    {
        dim3 grid(QW / BN, TT / BM);
        sgemm_bias_kernel<<<grid, 256>>>(aop, wo, nullptr, out, TT, QW, DD);
    }
}

// round 13
// speedup vs baseline: 1.9903x; 1.9903x over previous
#include <cuda_runtime.h>
#include <cuda_bf16.h>
#include <math.h>
#include <cstdint>

// ---------------------------------------------------------------------------
// Problem constants
// ---------------------------------------------------------------------------
#define TT   2048
#define DD   3584
#define NH   28
#define KVH  4
#define HD   128
#define GRP  7              // NH / KVH
#define KVW  (KVH*HD)       // 512
#define QW   (NH*HD)        // 3584

// ---------------------------------------------------------------------------
// Device scratch (no allocation allowed)
// ---------------------------------------------------------------------------
__device__ float g_q [TT * QW];
__device__ float g_k [TT * KVW];
__device__ float g_v [TT * KVW];
__device__ float g_ao[TT * QW];

__device__ __nv_bfloat16 g_xhi [TT * DD],   g_xlo [TT * DD];
__device__ __nv_bfloat16 g_aohi[TT * QW],   g_aolo[TT * QW];
__device__ __nv_bfloat16 g_wqT_hi[QW * DD], g_wqT_lo[QW * DD];
__device__ __nv_bfloat16 g_wkT_hi[KVW * DD], g_wkT_lo[KVW * DD];
__device__ __nv_bfloat16 g_wvT_hi[KVW * DD], g_wvT_lo[KVW * DD];
__device__ __nv_bfloat16 g_woT_hi[DD * QW], g_woT_lo[DD * QW];

// ---------------------------------------------------------------------------
// PTX helpers (portable: sm_80+ only, no arch-specific features)
// ---------------------------------------------------------------------------
__device__ __forceinline__ uint32_t smem_u32(const void* p) {
    uint32_t a;
    asm("{ .reg .u64 t; cvta.to.shared.u64 t, %1; cvt.u32.u64 %0, t; }"
        : "=r"(a) : "l"(p));
    return a;
}

__device__ __forceinline__ void cp16(uint32_t dst, const void* src) {
    asm volatile("cp.async.cg.shared.global [%0], [%1], 16;"
                 :: "r"(dst), "l"(src) : "memory");
}

__device__ __forceinline__ void ldsm4(uint32_t& r0, uint32_t& r1,
                                      uint32_t& r2, uint32_t& r3, uint32_t a) {
    asm volatile("ldmatrix.sync.aligned.m8n8.x4.shared.b16 {%0,%1,%2,%3}, [%4];"
                 : "=r"(r0), "=r"(r1), "=r"(r2), "=r"(r3) : "r"(a));
}

__device__ __forceinline__ void mma16816(float* d, const uint32_t* a,
                                         const uint32_t* b) {
    asm volatile(
        "mma.sync.aligned.m16n8k16.row.col.f32.bf16.bf16.f32 "
        "{%0,%1,%2,%3}, {%4,%5,%6,%7}, {%8,%9}, {%0,%1,%2,%3};"
        : "+f"(d[0]), "+f"(d[1]), "+f"(d[2]), "+f"(d[3])
        : "r"(a[0]), "r"(a[1]), "r"(a[2]), "r"(a[3]), "r"(b[0]), "r"(b[1]));
}

// ---------------------------------------------------------------------------
// bf16 split: hi = bf16(x), lo = bf16(x - hi)
// ---------------------------------------------------------------------------
__global__ void split_kernel(const float* __restrict__ in,
                             __nv_bfloat16* __restrict__ hi,
                             __nv_bfloat16* __restrict__ lo, int n4)
{
    int i = blockIdx.x * blockDim.x + threadIdx.x;
    if (i >= n4) return;
    float4 v = ((const float4*)in)[i];
    __nv_bfloat16 h0 = __float2bfloat16(v.x);
    __nv_bfloat16 h1 = __float2bfloat16(v.y);
    __nv_bfloat16 h2 = __float2bfloat16(v.z);
    __nv_bfloat16 h3 = __float2bfloat16(v.w);
    __nv_bfloat16 l0 = __float2bfloat16(v.x - __bfloat162float(h0));
    __nv_bfloat16 l1 = __float2bfloat16(v.y - __bfloat162float(h1));
    __nv_bfloat16 l2 = __float2bfloat16(v.z - __bfloat162float(h2));
    __nv_bfloat16 l3 = __float2bfloat16(v.w - __bfloat162float(h3));
    ((__nv_bfloat162*)hi)[i * 2 + 0] = __halves2bfloat162(h0, h1);
    ((__nv_bfloat162*)hi)[i * 2 + 1] = __halves2bfloat162(h2, h3);
    ((__nv_bfloat162*)lo)[i * 2 + 0] = __halves2bfloat162(l0, l1);
    ((__nv_bfloat162*)lo)[i * 2 + 1] = __halves2bfloat162(l2, l3);
}

// ---------------------------------------------------------------------------
// Transpose W[R][C] -> T[C][R] with bf16 hi/lo split. block (32,8), grid (C/32, R/32)
// ---------------------------------------------------------------------------
__global__ void transpose_split_kernel(const float* __restrict__ W,
                                       __nv_bfloat16* __restrict__ Thi,
                                       __nv_bfloat16* __restrict__ Tlo,
                                       int R, int Cc)
{
    __shared__ float t[32][33];
    const int bx = blockIdx.x, by = blockIdx.y;
    const int tx = threadIdx.x, ty = threadIdx.y;
    #pragma unroll
    for (int i = 0; i < 4; i++)
        t[ty + i * 8][tx] = W[(size_t)(by * 32 + ty + i * 8) * Cc + bx * 32 + tx];
    __syncthreads();
    #pragma unroll
    for (int i = 0; i < 4; i++) {
        float v = t[tx][ty + i * 8];
        __nv_bfloat16 h = __float2bfloat16(v);
        __nv_bfloat16 l = __float2bfloat16(v - __bfloat162float(h));
        size_t o = (size_t)(bx * 32 + ty + i * 8) * R + by * 32 + tx;
        Thi[o] = h;
        Tlo[o] = l;
    }
}

// ---------------------------------------------------------------------------
// mma.sync bf16x3 GEMM: C[m][n] = sum_k A[m][k]*Bt[n][k] (+bias[n])
// CTA tile 128x128, BK=32, 8 warps (4x2), warp tile 32x64.
// Smem: pitch 40 bf16 (80B) rows -> conflict-free ldmatrix; double-buffered cp.async.
// ---------------------------------------------------------------------------
#define PITCHB 80                    // bytes per smem row (32 bf16 + 8 pad)
#define ARR_B  (128 * PITCHB)        // 10240 B per operand tile
#define STAGE_B (4 * ARR_B)          // 40960 B per stage
#define GSMEM   (2 * STAGE_B)        // 81920 B

__global__ __launch_bounds__(256)
void gemm_bf16x3(const __nv_bfloat16* __restrict__ Ahi,
                 const __nv_bfloat16* __restrict__ Alo,
                 const __nv_bfloat16* __restrict__ Bhi,
                 const __nv_bfloat16* __restrict__ Blo,
                 const float* __restrict__ bias,
                 float* __restrict__ C, int K, int Ntot)
{
    extern __shared__ char smem[];
    const uint32_t sbase = smem_u32(smem);
    const int tid   = threadIdx.x;
    const int wid   = tid >> 5;
    const int lane  = tid & 31;
    const int warpM = wid >> 1;          // 0..3
    const int warpN = wid & 1;           // 0..1
    const int m0 = blockIdx.y * 128;
    const int n0 = blockIdx.x * 128;
    const int NS = K >> 5;               // stages of BK=32

    const size_t rb = (size_t)K * 2;     // row bytes
    const char* pAhi = (const char*)Ahi + (size_t)m0 * rb;
    const char* pAlo = (const char*)Alo + (size_t)m0 * rb;
    const char* pBhi = (const char*)Bhi + (size_t)n0 * rb;
    const char* pBlo = (const char*)Blo + (size_t)n0 * rb;

    float acc[2][8][4];
    #pragma unroll
    for (int i = 0; i < 2; i++)
        #pragma unroll
        for (int j = 0; j < 8; j++)
            #pragma unroll
            for (int r = 0; r < 4; r++) acc[i][j][r] = 0.f;

    // stage loader: each array is 128 rows x 64B = 512 chunks of 16B
    auto load_stage = [&](int s, int b) {
        const uint32_t t0 = sbase + b * STAGE_B;
        const size_t koff = (size_t)s * 64;
        #pragma unroll
        for (int t = 0; t < 2; t++) {
            int idx = tid + t * 256;          // 0..511
            int row = idx >> 2;
            int ch  = (idx & 3) << 4;
            uint32_t so = row * PITCHB + ch;
            size_t g = (size_t)row * rb + koff + ch;
            cp16(t0 +             so, pAhi + g);
            cp16(t0 + ARR_B +     so, pAlo + g);
            cp16(t0 + 2 * ARR_B + so, pBhi + g);
            cp16(t0 + 3 * ARR_B + so, pBlo + g);
        }
        asm volatile("cp.async.commit_group;" ::: "memory");
    };

    load_stage(0, 0);

    const int lrow = lane & 15;
    const int lcolh = (lane >> 4) << 4;   // 0 or 16 bytes

    for (int s = 0; s < NS; s++) {
        if (s + 1 < NS) {
            load_stage(s + 1, (s + 1) & 1);
            asm volatile("cp.async.wait_group 1;" ::: "memory");
        } else {
            asm volatile("cp.async.wait_group 0;" ::: "memory");
        }
        __syncthreads();

        const uint32_t bb = sbase + (s & 1) * STAGE_B;
        const uint32_t sAh = bb;
        const uint32_t sAl = bb + ARR_B;
        const uint32_t sBh = bb + 2 * ARR_B;
        const uint32_t sBl = bb + 3 * ARR_B;

        #pragma unroll
        for (int kc = 0; kc < 2; kc++) {
            const uint32_t ko = kc * 32;   // byte offset of k-chunk

            uint32_t ah[2][4], al[2][4];
            #pragma unroll
            for (int mi = 0; mi < 2; mi++) {
                uint32_t ra = (warpM * 32 + mi * 16 + lrow) * PITCHB + ko + lcolh;
                ldsm4(ah[mi][0], ah[mi][1], ah[mi][2], ah[mi][3], sAh + ra);
                ldsm4(al[mi][0], al[mi][1], al[mi][2], al[mi][3], sAl + ra);
            }

            uint32_t bh[8][2], bl[8][2];
            #pragma unroll
            for (int bi = 0; bi < 4; bi++) {
                uint32_t rbv = (warpN * 64 + bi * 16 + lrow) * PITCHB + ko + lcolh;
                uint32_t t0, t1, t2, t3;
                ldsm4(t0, t1, t2, t3, sBh + rbv);
                bh[bi * 2][0] = t0; bh[bi * 2][1] = t2;
                bh[bi * 2 + 1][0] = t1; bh[bi * 2 + 1][1] = t3;
                ldsm4(t0, t1, t2, t3, sBl + rbv);
                bl[bi * 2][0] = t0; bl[bi * 2][1] = t2;
                bl[bi * 2 + 1][0] = t1; bl[bi * 2 + 1][1] = t3;
            }

            #pragma unroll
            for (int mi = 0; mi < 2; mi++)
                #pragma unroll
                for (int j = 0; j < 8; j++) {
                    mma16816(acc[mi][j], ah[mi], bh[j]);
                    mma16816(acc[mi][j], ah[mi], bl[j]);
                    mma16816(acc[mi][j], al[mi], bh[j]);
                }
        }
        __syncthreads();
    }

    // epilogue: d0,d1 -> row m+(lane>>2), cols (lane&3)*2,+1 ; d2,d3 -> row m+8
    #pragma unroll
    for (int mi = 0; mi < 2; mi++) {
        #pragma unroll
        for (int j = 0; j < 8; j++) {
            int r  = m0 + warpM * 32 + mi * 16 + (lane >> 2);
            int c  = n0 + warpN * 64 + j * 8 + (lane & 3) * 2;
            float b0 = bias ? bias[c]     : 0.f;
            float b1 = bias ? bias[c + 1] : 0.f;
            float2 v0 = { acc[mi][j][0] + b0, acc[mi][j][1] + b1 };
            float2 v1 = { acc[mi][j][2] + b0, acc[mi][j][3] + b1 };
            *(float2*)(C + (size_t)r * Ntot + c)       = v0;
            *(float2*)(C + (size_t)(r + 8) * Ntot + c) = v1;
        }
    }
}

// ---------------------------------------------------------------------------
// RoPE (in-place)
// ---------------------------------------------------------------------------
__global__ void rope_kernel(float* __restrict__ buf,
                            const float* __restrict__ sinT,
                            const float* __restrict__ cosT,
                            int nheads)
{
    int idx = blockIdx.x * blockDim.x + threadIdx.x;
    int total = TT * nheads * (HD / 2);
    if (idx >= total) return;
    int i = idx & 63;
    int h = (idx >> 6) % nheads;
    int t = idx / (64 * nheads);

    float* p = buf + (size_t)t * (nheads * HD) + h * HD;
    float x1 = p[i];
    float x2 = p[i + 64];
    float s = sinT[t * 64 + i];
    float c = cosT[t * 64 + i];
    p[i]      = x1 * c - x2 * s;
    p[i + 64] = x2 * c + x1 * s;
}

// ---------------------------------------------------------------------------
// Flash attention (fp32, causal, GQA) — unchanged known-good kernel
// ---------------------------------------------------------------------------
#define AT_BM 64
#define AT_BN 64
#define QK_PITCH 68

#define ATT_SMEM_FLOATS (2 * HD * QK_PITCH + AT_BN * HD + AT_BM * AT_BN)

__global__ __launch_bounds__(256, 1)
void attn_kernel(const float* __restrict__ qb, const float* __restrict__ kb,
                 const float* __restrict__ vb, float* __restrict__ ob)
{
    extern __shared__ float sm[];
    float* Qst = sm;
    float* Kst = Qst + HD * QK_PITCH;
    float* Vs  = Kst + HD * QK_PITCH;
    float* Ps  = Vs  + AT_BN * HD;

    const int tid = threadIdx.x;
    const int tx  = tid & 15;
    const int ty  = tid >> 4;
    const int qi  = blockIdx.x;
    const int n   = blockIdx.y;
    const int kh  = n / GRP;
    const int q0  = qi * AT_BM;

    #pragma unroll
    for (int it = 0; it < 8; it++) {
        int idx = (it * 256 + tid) * 4;
        int row = idx >> 7;
        int h   = idx & 127;
        float4 v = *(const float4*)(qb + (size_t)(q0 + row) * QW + n * HD + h);
        Qst[(h + 0) * QK_PITCH + row] = v.x;
        Qst[(h + 1) * QK_PITCH + row] = v.y;
        Qst[(h + 2) * QK_PITCH + row] = v.z;
        Qst[(h + 3) * QK_PITCH + row] = v.w;
    }

    float m_reg[4], l_reg[4], acc[4][8];
    #pragma unroll
    for (int i = 0; i < 4; i++) {
        m_reg[i] = -1e30f; l_reg[i] = 0.f;
        #pragma unroll
        for (int j = 0; j < 8; j++) acc[i][j] = 0.f;
    }

    const float scale = 0.08838834764831845f;

    for (int kbk = 0; kbk <= qi; kbk++) {
        const int k0 = kbk * AT_BN;
        __syncthreads();

        #pragma unroll
        for (int it = 0; it < 8; it++) {
            int idx = (it * 256 + tid) * 4;
            int row = idx >> 7;
            int h   = idx & 127;
            float4 vk = *(const float4*)(kb + (size_t)(k0 + row) * KVW + kh * HD + h);
            Kst[(h + 0) * QK_PITCH + row] = vk.x;
            Kst[(h + 1) * QK_PITCH + row] = vk.y;
            Kst[(h + 2) * QK_PITCH + row] = vk.z;
            Kst[(h + 3) * QK_PITCH + row] = vk.w;
            float4 vv = *(const float4*)(vb + (size_t)(k0 + row) * KVW + kh * HD + h);
            *(float4*)(Vs + row * HD + h) = vv;
        }
        __syncthreads();

        float s[4][4];
        #pragma unroll
        for (int i = 0; i < 4; i++)
            #pragma unroll
            for (int j = 0; j < 4; j++) s[i][j] = 0.f;

        #pragma unroll 8
        for (int kk = 0; kk < HD; kk++) {
            float4 qr = *(float4*)(Qst + kk * QK_PITCH + ty * 4);
            float4 kr = *(float4*)(Kst + kk * QK_PITCH + tx * 4);
            s[0][0] += qr.x * kr.x; s[0][1] += qr.x * kr.y; s[0][2] += qr.x * kr.z; s[0][3] += qr.x * kr.w;
            s[1][0] += qr.y * kr.x; s[1][1] += qr.y * kr.y; s[1][2] += qr.y * kr.z; s[1][3] += qr.y * kr.w;
            s[2][0] += qr.z * kr.x; s[2][1] += qr.z * kr.y; s[2][2] += qr.z * kr.z; s[2][3] += qr.z * kr.w;
            s[3][0] += qr.w * kr.x; s[3][1] += qr.w * kr.y; s[3][2] += qr.w * kr.z; s[3][3] += qr.w * kr.w;
        }

        #pragma unroll
        for (int i = 0; i < 4; i++) {
            const int gq = q0 + ty * 4 + i;
            float rmax = -1e30f;
            #pragma unroll
            for (int j = 0; j < 4; j++) {
                int gk = k0 + tx * 4 + j;
                float sv = s[i][j] * scale;
                if (gk > gq) sv = -1e30f;
                s[i][j] = sv;
                rmax = fmaxf(rmax, sv);
            }
            #pragma unroll
            for (int off = 8; off > 0; off >>= 1)
                rmax = fmaxf(rmax, __shfl_xor_sync(0xffffffffu, rmax, off));

            float m_new = fmaxf(m_reg[i], rmax);
            float alpha = __expf(m_reg[i] - m_new);

            float rsum = 0.f;
            #pragma unroll
            for (int j = 0; j < 4; j++) {
                float p = __expf(s[i][j] - m_new);
                s[i][j] = p;
                rsum += p;
            }
            #pragma unroll
            for (int off = 8; off > 0; off >>= 1)
                rsum += __shfl_xor_sync(0xffffffffu, rsum, off);

            l_reg[i] = l_reg[i] * alpha + rsum;
            m_reg[i] = m_new;

            #pragma unroll
            for (int j = 0; j < 8; j++) acc[i][j] *= alpha;

            #pragma unroll
            for (int j = 0; j < 4; j++)
                Ps[(ty * 4 + i) * AT_BN + tx * 4 + j] = s[i][j];
        }
        __syncthreads();

        #pragma unroll 4
        for (int kk = 0; kk < AT_BN; kk++) {
            float4 v0 = *(float4*)(Vs + kk * HD + tx * 8);
            float4 v1 = *(float4*)(Vs + kk * HD + tx * 8 + 4);
            float p0 = Ps[(ty * 4 + 0) * AT_BN + kk];
            float p1 = Ps[(ty * 4 + 1) * AT_BN + kk];
            float p2 = Ps[(ty * 4 + 2) * AT_BN + kk];
            float p3 = Ps[(ty * 4 + 3) * AT_BN + kk];
            acc[0][0] += p0 * v0.x; acc[0][1] += p0 * v0.y; acc[0][2] += p0 * v0.z; acc[0][3] += p0 * v0.w;
            acc[0][4] += p0 * v1.x; acc[0][5] += p0 * v1.y; acc[0][6] += p0 * v1.z; acc[0][7] += p0 * v1.w;
            acc[1][0] += p1 * v0.x; acc[1][1] += p1 * v0.y; acc[1][2] += p1 * v0.z; acc[1][3] += p1 * v0.w;
            acc[1][4] += p1 * v1.x; acc[1][5] += p1 * v1.y; acc[1][6] += p1 * v1.z; acc[1][7] += p1 * v1.w;
            acc[2][0] += p2 * v0.x; acc[2][1] += p2 * v0.y; acc[2][2] += p2 * v0.z; acc[2][3] += p2 * v0.w;
            acc[2][4] += p2 * v1.x; acc[2][5] += p2 * v1.y; acc[2][6] += p2 * v1.z; acc[2][7] += p2 * v1.w;
            acc[3][0] += p3 * v0.x; acc[3][1] += p3 * v0.y; acc[3][2] += p3 * v0.z; acc[3][3] += p3 * v0.w;
            acc[3][4] += p3 * v1.x; acc[3][5] += p3 * v1.y; acc[3][6] += p3 * v1.z; acc[3][7] += p3 * v1.w;
        }
    }

    #pragma unroll
    for (int i = 0; i < 4; i++) {
        float inv = 1.f / l_reg[i];
        const size_t row = q0 + ty * 4 + i;
        float* orow = ob + row * QW + n * HD + tx * 8;
        float4 v0, v1;
        v0.x = acc[i][0] * inv; v0.y = acc[i][1] * inv;
        v0.z = acc[i][2] * inv; v0.w = acc[i][3] * inv;
        v1.x = acc[i][4] * inv; v1.y = acc[i][5] * inv;
        v1.z = acc[i][6] * inv; v1.w = acc[i][7] * inv;
        *(float4*)(orow)     = v0;
        *(float4*)(orow + 4) = v1;
    }
}

// ---------------------------------------------------------------------------
// Launch
//   inputs: 0:x 1:attn_mask 2:sin 3:cos 4:wq 5:wk 6:wv 7:wo 8:q_bias 9:k_bias 10:v_bias
// ---------------------------------------------------------------------------
extern "C" void kernel_launch(void* const* d_in, const int* in_sizes, int n_in,
                              void* d_out, int out_size)
{
    const float* x      = (const float*)d_in[0];
    const float* sinT   = (const float*)d_in[2];
    const float* cosT   = (const float*)d_in[3];
    const float* wq     = (const float*)d_in[4];
    const float* wk     = (const float*)d_in[5];
    const float* wv     = (const float*)d_in[6];
    const float* wo     = (const float*)d_in[7];
    const float* q_bias = (const float*)d_in[8];
    const float* k_bias = (const float*)d_in[9];
    const float* v_bias = (const float*)d_in[10];
    float* out = (float*)d_out;

    float *qp, *kp, *vp, *aop;
    cudaGetSymbolAddress((void**)&qp,  g_q);
    cudaGetSymbolAddress((void**)&kp,  g_k);
    cudaGetSymbolAddress((void**)&vp,  g_v);
    cudaGetSymbolAddress((void**)&aop, g_ao);

    __nv_bfloat16 *xhi, *xlo, *aohi, *aolo;
    __nv_bfloat16 *wqh, *wql, *wkh, *wkl, *wvh, *wvl, *woh, *wol;
    cudaGetSymbolAddress((void**)&xhi,  g_xhi);
    cudaGetSymbolAddress((void**)&xlo,  g_xlo);
    cudaGetSymbolAddress((void**)&aohi, g_aohi);
    cudaGetSymbolAddress((void**)&aolo, g_aolo);
    cudaGetSymbolAddress((void**)&wqh,  g_wqT_hi);
    cudaGetSymbolAddress((void**)&wql,  g_wqT_lo);
    cudaGetSymbolAddress((void**)&wkh,  g_wkT_hi);
    cudaGetSymbolAddress((void**)&wkl,  g_wkT_lo);
    cudaGetSymbolAddress((void**)&wvh,  g_wvT_hi);
    cudaGetSymbolAddress((void**)&wvl,  g_wvT_lo);
    cudaGetSymbolAddress((void**)&woh,  g_woT_hi);
    cudaGetSymbolAddress((void**)&wol,  g_woT_lo);

    cudaFuncSetAttribute(gemm_bf16x3,
                         cudaFuncAttributeMaxDynamicSharedMemorySize, GSMEM);

    // 1) operand prep: split x; transpose+split weights
    {
        int n4 = TT * DD / 4;
        split_kernel<<<(n4 + 255) / 256, 256>>>(x, xhi, xlo, n4);

        dim3 blk(32, 8);
        transpose_split_kernel<<<dim3(QW / 32, DD / 32),  blk>>>(wq, wqh, wql, DD, QW);
        transpose_split_kernel<<<dim3(KVW / 32, DD / 32), blk>>>(wk, wkh, wkl, DD, KVW);
        transpose_split_kernel<<<dim3(KVW / 32, DD / 32), blk>>>(wv, wvh, wvl, DD, KVW);
        transpose_split_kernel<<<dim3(DD / 32, QW / 32),  blk>>>(wo, woh, wol, QW, DD);
    }

    // 2) QKV projections on tensor cores (mma.sync bf16x3)
    gemm_bf16x3<<<dim3(QW / 128,  TT / 128), 256, GSMEM>>>(xhi, xlo, wqh, wql, q_bias, qp, DD, QW);
    gemm_bf16x3<<<dim3(KVW / 128, TT / 128), 256, GSMEM>>>(xhi, xlo, wkh, wkl, k_bias, kp, DD, KVW);
    gemm_bf16x3<<<dim3(KVW / 128, TT / 128), 256, GSMEM>>>(xhi, xlo, wvh, wvl, v_bias, vp, DD, KVW);

    // 3) RoPE
    {
        int totq = TT * NH * (HD / 2);
        rope_kernel<<<(totq + 255) / 256, 256>>>(qp, sinT, cosT, NH);
        int totk = TT * KVH * (HD / 2);
        rope_kernel<<<(totk + 255) / 256, 256>>>(kp, sinT, cosT, KVH);
    }

    // 4) Attention (fp32)
    {
        const size_t smem = ATT_SMEM_FLOATS * sizeof(float);
        cudaFuncSetAttribute(attn_kernel,
                             cudaFuncAttributeMaxDynamicSharedMemorySize,
                             (int)smem);
        dim3 grid(TT / AT_BM, NH);
        attn_kernel<<<grid, 256, smem>>>(qp, kp, vp, aop);
    }

    // 5) Output projection on tensor cores
    {
        int n4 = TT * QW / 4;
        split_kernel<<<(n4 + 255) / 256, 256>>>(aop, aohi, aolo, n4);
        gemm_bf16x3<<<dim3(QW / 128, TT / 128), 256, GSMEM>>>(aohi, aolo, woh, wol, nullptr, out, QW, QW);
    }
}

// round 15
// speedup vs baseline: 3.2055x; 1.6106x over previous
#include <cuda_runtime.h>
#include <cuda_bf16.h>
#include <math.h>
#include <cstdint>

// ---------------------------------------------------------------------------
// Problem constants
// ---------------------------------------------------------------------------
#define TT   2048
#define DD   3584
#define NH   28
#define KVH  4
#define HD   128
#define GRP  7              // NH / KVH
#define KVW  (KVH*HD)       // 512
#define QW   (NH*HD)        // 3584

// ---------------------------------------------------------------------------
// Device scratch (no allocation allowed)
// ---------------------------------------------------------------------------
__device__ float g_q [TT * QW];
__device__ float g_k [TT * KVW];
__device__ float g_v [TT * KVW];
__device__ float g_ao[TT * QW];

__device__ __nv_bfloat16 g_xhi [TT * DD],   g_xlo [TT * DD];
__device__ __nv_bfloat16 g_aohi[TT * QW],   g_aolo[TT * QW];
__device__ __nv_bfloat16 g_qhi [TT * QW],   g_qlo [TT * QW];
__device__ __nv_bfloat16 g_khi [TT * KVW],  g_klo [TT * KVW];
__device__ __nv_bfloat16 g_vhi [TT * KVW],  g_vlo [TT * KVW];
__device__ __nv_bfloat16 g_wqT_hi[QW * DD], g_wqT_lo[QW * DD];
__device__ __nv_bfloat16 g_wkT_hi[KVW * DD], g_wkT_lo[KVW * DD];
__device__ __nv_bfloat16 g_wvT_hi[KVW * DD], g_wvT_lo[KVW * DD];
__device__ __nv_bfloat16 g_woT_hi[DD * QW], g_woT_lo[DD * QW];

// ---------------------------------------------------------------------------
// PTX helpers (portable: sm_80+ only, no arch-specific features)
// ---------------------------------------------------------------------------
__device__ __forceinline__ uint32_t smem_u32(const void* p) {
    uint32_t a;
    asm("{ .reg .u64 t; cvta.to.shared.u64 t, %1; cvt.u32.u64 %0, t; }"
        : "=r"(a) : "l"(p));
    return a;
}

__device__ __forceinline__ void cp16(uint32_t dst, const void* src) {
    asm volatile("cp.async.cg.shared.global [%0], [%1], 16;"
                 :: "r"(dst), "l"(src) : "memory");
}

__device__ __forceinline__ void ldsm4(uint32_t& r0, uint32_t& r1,
                                      uint32_t& r2, uint32_t& r3, uint32_t a) {
    asm volatile("ldmatrix.sync.aligned.m8n8.x4.shared.b16 {%0,%1,%2,%3}, [%4];"
                 : "=r"(r0), "=r"(r1), "=r"(r2), "=r"(r3) : "r"(a));
}

__device__ __forceinline__ void ldsm4t(uint32_t& r0, uint32_t& r1,
                                       uint32_t& r2, uint32_t& r3, uint32_t a) {
    asm volatile("ldmatrix.sync.aligned.m8n8.x4.trans.shared.b16 {%0,%1,%2,%3}, [%4];"
                 : "=r"(r0), "=r"(r1), "=r"(r2), "=r"(r3) : "r"(a));
}

__device__ __forceinline__ void mma16816(float* d, const uint32_t* a,
                                         const uint32_t* b) {
    asm volatile(
        "mma.sync.aligned.m16n8k16.row.col.f32.bf16.bf16.f32 "
        "{%0,%1,%2,%3}, {%4,%5,%6,%7}, {%8,%9}, {%0,%1,%2,%3};"
        : "+f"(d[0]), "+f"(d[1]), "+f"(d[2]), "+f"(d[3])
        : "r"(a[0]), "r"(a[1]), "r"(a[2]), "r"(a[3]), "r"(b[0]), "r"(b[1]));
}

__device__ __forceinline__ uint32_t pack_bf16x2(float x, float y) {
    __nv_bfloat162 h = __floats2bfloat162_rn(x, y);
    return *(uint32_t*)&h;
}

// ---------------------------------------------------------------------------
// bf16 split: hi = bf16(x), lo = bf16(x - hi)
// ---------------------------------------------------------------------------
__global__ void split_kernel(const float* __restrict__ in,
                             __nv_bfloat16* __restrict__ hi,
                             __nv_bfloat16* __restrict__ lo, int n4)
{
    int i = blockIdx.x * blockDim.x + threadIdx.x;
    if (i >= n4) return;
    float4 v = ((const float4*)in)[i];
    __nv_bfloat16 h0 = __float2bfloat16(v.x);
    __nv_bfloat16 h1 = __float2bfloat16(v.y);
    __nv_bfloat16 h2 = __float2bfloat16(v.z);
    __nv_bfloat16 h3 = __float2bfloat16(v.w);
    __nv_bfloat16 l0 = __float2bfloat16(v.x - __bfloat162float(h0));
    __nv_bfloat16 l1 = __float2bfloat16(v.y - __bfloat162float(h1));
    __nv_bfloat16 l2 = __float2bfloat16(v.z - __bfloat162float(h2));
    __nv_bfloat16 l3 = __float2bfloat16(v.w - __bfloat162float(h3));
    ((__nv_bfloat162*)hi)[i * 2 + 0] = __halves2bfloat162(h0, h1);
    ((__nv_bfloat162*)hi)[i * 2 + 1] = __halves2bfloat162(h2, h3);
    ((__nv_bfloat162*)lo)[i * 2 + 0] = __halves2bfloat162(l0, l1);
    ((__nv_bfloat162*)lo)[i * 2 + 1] = __halves2bfloat162(l2, l3);
}

// ---------------------------------------------------------------------------
// Transpose W[R][C] -> T[C][R] with bf16 hi/lo split. block (32,8), grid (C/32, R/32)
// ---------------------------------------------------------------------------
__global__ void transpose_split_kernel(const float* __restrict__ W,
                                       __nv_bfloat16* __restrict__ Thi,
                                       __nv_bfloat16* __restrict__ Tlo,
                                       int R, int Cc)
{
    __shared__ float t[32][33];
    const int bx = blockIdx.x, by = blockIdx.y;
    const int tx = threadIdx.x, ty = threadIdx.y;
    #pragma unroll
    for (int i = 0; i < 4; i++)
        t[ty + i * 8][tx] = W[(size_t)(by * 32 + ty + i * 8) * Cc + bx * 32 + tx];
    __syncthreads();
    #pragma unroll
    for (int i = 0; i < 4; i++) {
        float v = t[tx][ty + i * 8];
        __nv_bfloat16 h = __float2bfloat16(v);
        __nv_bfloat16 l = __float2bfloat16(v - __bfloat162float(h));
        size_t o = (size_t)(bx * 32 + ty + i * 8) * R + by * 32 + tx;
        Thi[o] = h;
        Tlo[o] = l;
    }
}

// ---------------------------------------------------------------------------
// Fused RoPE + bf16 hi/lo split: reads fp32 proj, writes rotated bf16 hi/lo.
// One thread per (t, head, pair i<64).
// ---------------------------------------------------------------------------
__global__ void rope_split_kernel(const float* __restrict__ buf,
                                  const float* __restrict__ sinT,
                                  const float* __restrict__ cosT,
                                  __nv_bfloat16* __restrict__ hi,
                                  __nv_bfloat16* __restrict__ lo,
                                  int nheads)
{
    int idx = blockIdx.x * blockDim.x + threadIdx.x;
    int total = TT * nheads * (HD / 2);
    if (idx >= total) return;
    int i = idx & 63;
    int h = (idx >> 6) % nheads;
    int t = idx / (64 * nheads);

    size_t off = (size_t)t * (nheads * HD) + h * HD;
    float x1 = buf[off + i];
    float x2 = buf[off + i + 64];
    float s = sinT[t * 64 + i];
    float c = cosT[t * 64 + i];
    float y1 = x1 * c - x2 * s;
    float y2 = x2 * c + x1 * s;

    __nv_bfloat16 h1 = __float2bfloat16(y1);
    __nv_bfloat16 h2 = __float2bfloat16(y2);
    hi[off + i]      = h1;
    hi[off + i + 64] = h2;
    lo[off + i]      = __float2bfloat16(y1 - __bfloat162float(h1));
    lo[off + i + 64] = __float2bfloat16(y2 - __bfloat162float(h2));
}

// ---------------------------------------------------------------------------
// mma.sync bf16x3 GEMM: C[m][n] = sum_k A[m][k]*Bt[n][k] (+bias[n])
// CTA tile 128x128, BK=32, 8 warps (4x2), warp tile 32x64.
// ---------------------------------------------------------------------------
#define PITCHB 80                    // bytes per smem row (32 bf16 + 8 pad)
#define ARR_B  (128 * PITCHB)
#define STAGE_B (4 * ARR_B)
#define GSMEM   (2 * STAGE_B)

__global__ __launch_bounds__(256)
void gemm_bf16x3(const __nv_bfloat16* __restrict__ Ahi,
                 const __nv_bfloat16* __restrict__ Alo,
                 const __nv_bfloat16* __restrict__ Bhi,
                 const __nv_bfloat16* __restrict__ Blo,
                 const float* __restrict__ bias,
                 float* __restrict__ C, int K, int Ntot)
{
    extern __shared__ char smem[];
    const uint32_t sbase = smem_u32(smem);
    const int tid   = threadIdx.x;
    const int wid   = tid >> 5;
    const int lane  = tid & 31;
    const int warpM = wid >> 1;
    const int warpN = wid & 1;
    const int m0 = blockIdx.y * 128;
    const int n0 = blockIdx.x * 128;
    const int NS = K >> 5;

    const size_t rb = (size_t)K * 2;
    const char* pAhi = (const char*)Ahi + (size_t)m0 * rb;
    const char* pAlo = (const char*)Alo + (size_t)m0 * rb;
    const char* pBhi = (const char*)Bhi + (size_t)n0 * rb;
    const char* pBlo = (const char*)Blo + (size_t)n0 * rb;

    float acc[2][8][4];
    #pragma unroll
    for (int i = 0; i < 2; i++)
        #pragma unroll
        for (int j = 0; j < 8; j++)
            #pragma unroll
            for (int r = 0; r < 4; r++) acc[i][j][r] = 0.f;

    auto load_stage = [&](int s, int b) {
        const uint32_t t0 = sbase + b * STAGE_B;
        const size_t koff = (size_t)s * 64;
        #pragma unroll
        for (int t = 0; t < 2; t++) {
            int idx = tid + t * 256;
            int row = idx >> 2;
            int ch  = (idx & 3) << 4;
            uint32_t so = row * PITCHB + ch;
            size_t g = (size_t)row * rb + koff + ch;
            cp16(t0 +             so, pAhi + g);
            cp16(t0 + ARR_B +     so, pAlo + g);
            cp16(t0 + 2 * ARR_B + so, pBhi + g);
            cp16(t0 + 3 * ARR_B + so, pBlo + g);
        }
        asm volatile("cp.async.commit_group;" ::: "memory");
    };

    load_stage(0, 0);

    const int lrow = lane & 15;
    const int lcolh = (lane >> 4) << 4;

    for (int s = 0; s < NS; s++) {
        if (s + 1 < NS) {
            load_stage(s + 1, (s + 1) & 1);
            asm volatile("cp.async.wait_group 1;" ::: "memory");
        } else {
            asm volatile("cp.async.wait_group 0;" ::: "memory");
        }
        __syncthreads();

        const uint32_t bb = sbase + (s & 1) * STAGE_B;
        const uint32_t sAh = bb;
        const uint32_t sAl = bb + ARR_B;
        const uint32_t sBh = bb + 2 * ARR_B;
        const uint32_t sBl = bb + 3 * ARR_B;

        #pragma unroll
        for (int kc = 0; kc < 2; kc++) {
            const uint32_t ko = kc * 32;

            uint32_t ah[2][4], al[2][4];
            #pragma unroll
            for (int mi = 0; mi < 2; mi++) {
                uint32_t ra = (warpM * 32 + mi * 16 + lrow) * PITCHB + ko + lcolh;
                ldsm4(ah[mi][0], ah[mi][1], ah[mi][2], ah[mi][3], sAh + ra);
                ldsm4(al[mi][0], al[mi][1], al[mi][2], al[mi][3], sAl + ra);
            }

            uint32_t bh[8][2], bl[8][2];
            #pragma unroll
            for (int bi = 0; bi < 4; bi++) {
                uint32_t rbv = (warpN * 64 + bi * 16 + lrow) * PITCHB + ko + lcolh;
                uint32_t t0, t1, t2, t3;
                ldsm4(t0, t1, t2, t3, sBh + rbv);
                bh[bi * 2][0] = t0; bh[bi * 2][1] = t2;
                bh[bi * 2 + 1][0] = t1; bh[bi * 2 + 1][1] = t3;
                ldsm4(t0, t1, t2, t3, sBl + rbv);
                bl[bi * 2][0] = t0; bl[bi * 2][1] = t2;
                bl[bi * 2 + 1][0] = t1; bl[bi * 2 + 1][1] = t3;
            }

            #pragma unroll
            for (int mi = 0; mi < 2; mi++)
                #pragma unroll
                for (int j = 0; j < 8; j++) {
                    mma16816(acc[mi][j], ah[mi], bh[j]);
                    mma16816(acc[mi][j], ah[mi], bl[j]);
                    mma16816(acc[mi][j], al[mi], bh[j]);
                }
        }
        __syncthreads();
    }

    #pragma unroll
    for (int mi = 0; mi < 2; mi++) {
        #pragma unroll
        for (int j = 0; j < 8; j++) {
            int r  = m0 + warpM * 32 + mi * 16 + (lane >> 2);
            int c  = n0 + warpN * 64 + j * 8 + (lane & 3) * 2;
            float b0 = bias ? bias[c]     : 0.f;
            float b1 = bias ? bias[c + 1] : 0.f;
            float2 v0 = { acc[mi][j][0] + b0, acc[mi][j][1] + b1 };
            float2 v1 = { acc[mi][j][2] + b0, acc[mi][j][3] + b1 };
            *(float2*)(C + (size_t)r * Ntot + c)       = v0;
            *(float2*)(C + (size_t)(r + 8) * Ntot + c) = v1;
        }
    }
}

// ---------------------------------------------------------------------------
// Tensor-core flash attention (bf16x3, causal, GQA).
// Tile 64 q-rows x 64 kv-cols, HD=128. 128 threads = 4 warps, warp = 16 rows.
// QK^T: A = Q (row-major [m][k]), B = K stored [n=kv][k=hd] -> non-trans ldsm.
// PV:   A = P (from S fragments), B = V stored [k=kv][n=hd] -> trans ldsm.
// ---------------------------------------------------------------------------
#define APITCH 272                        // bytes per 128-bf16 smem row
#define AARR   (64 * APITCH)              // 17408 B per array
#define ASMEM  (6 * AARR)                 // 104448 B

__global__ __launch_bounds__(128)
void attn_mma(const __nv_bfloat16* __restrict__ qhi, const __nv_bfloat16* __restrict__ qlo,
              const __nv_bfloat16* __restrict__ khi, const __nv_bfloat16* __restrict__ klo,
              const __nv_bfloat16* __restrict__ vhi, const __nv_bfloat16* __restrict__ vlo,
              float* __restrict__ ob)
{
    extern __shared__ char sm8[];
    const uint32_t sQh = smem_u32(sm8);
    const uint32_t sQl = sQh + AARR;
    const uint32_t sKh = sQl + AARR;
    const uint32_t sKl = sKh + AARR;
    const uint32_t sVh = sKl + AARR;
    const uint32_t sVl = sVh + AARR;

    const int tid = threadIdx.x, wid = tid >> 5, lane = tid & 31;
    const int qi = blockIdx.x, n = blockIdx.y, kh = n / GRP;
    const int q0 = qi * 64;

    // load Q hi/lo: 64 rows x 256B
    {
        const char* gqh = (const char*)(qhi + (size_t)q0 * QW + n * HD);
        const char* gql = (const char*)(qlo + (size_t)q0 * QW + n * HD);
        #pragma unroll
        for (int t = 0; t < 8; t++) {
            int idx = tid + t * 128;
            int row = idx >> 4;
            int ch  = (idx & 15) << 4;
            size_t g = (size_t)row * QW * 2 + ch;
            cp16(sQh + row * APITCH + ch, gqh + g);
            cp16(sQl + row * APITCH + ch, gql + g);
        }
        asm volatile("cp.async.commit_group;" ::: "memory");
    }

    float m0 = -1e30f, m1 = -1e30f, l0 = 0.f, l1 = 0.f;
    float o[16][4];
    #pragma unroll
    for (int j = 0; j < 16; j++)
        #pragma unroll
        for (int r = 0; r < 4; r++) o[j][r] = 0.f;

    const float scale = 0.08838834764831845f;   // 1/sqrt(128)
    const int lr  = lane & 15;
    const int lch = (lane >> 4) << 4;
    const int r0w = wid * 16 + (lane >> 2);     // warp-local row of c0/c1
    const int gr0 = q0 + r0w;
    const int gr1 = gr0 + 8;

    for (int kbk = 0; kbk <= qi; kbk++) {
        const int k0 = kbk * 64;
        __syncthreads();     // previous iteration's smem consumers done

        {
            const char* gkh = (const char*)(khi + (size_t)k0 * KVW + kh * HD);
            const char* gkl = (const char*)(klo + (size_t)k0 * KVW + kh * HD);
            const char* gvh = (const char*)(vhi + (size_t)k0 * KVW + kh * HD);
            const char* gvl = (const char*)(vlo + (size_t)k0 * KVW + kh * HD);
            #pragma unroll
            for (int t = 0; t < 8; t++) {
                int idx = tid + t * 128;
                int row = idx >> 4;
                int ch  = (idx & 15) << 4;
                size_t g = (size_t)row * KVW * 2 + ch;
                uint32_t so = row * APITCH + ch;
                cp16(sKh + so, gkh + g);
                cp16(sKl + so, gkl + g);
                cp16(sVh + so, gvh + g);
                cp16(sVl + so, gvl + g);
            }
            asm volatile("cp.async.commit_group;" ::: "memory");
            asm volatile("cp.async.wait_group 0;" ::: "memory");
        }
        __syncthreads();

        // ---- S = Q K^T (bf16x3) ----
        float s[8][4];
        #pragma unroll
        for (int j = 0; j < 8; j++)
            #pragma unroll
            for (int r = 0; r < 4; r++) s[j][r] = 0.f;

        #pragma unroll
        for (int kc = 0; kc < 8; kc++) {
            uint32_t qa = (wid * 16 + lr) * APITCH + kc * 32 + lch;
            uint32_t ah[4], al[4];
            ldsm4(ah[0], ah[1], ah[2], ah[3], sQh + qa);
            ldsm4(al[0], al[1], al[2], al[3], sQl + qa);
            #pragma unroll
            for (int bi = 0; bi < 4; bi++) {
                uint32_t ka = (bi * 16 + lr) * APITCH + kc * 32 + lch;
                uint32_t t0, t1, t2, t3, u0, u1, u2, u3;
                ldsm4(t0, t1, t2, t3, sKh + ka);
                ldsm4(u0, u1, u2, u3, sKl + ka);
                uint32_t bh0[2] = {t0, t2}, bh1[2] = {t1, t3};
                uint32_t bl0[2] = {u0, u2}, bl1[2] = {u1, u3};
                mma16816(s[2 * bi],     ah, bh0);
                mma16816(s[2 * bi],     ah, bl0);
                mma16816(s[2 * bi],     al, bh0);
                mma16816(s[2 * bi + 1], ah, bh1);
                mma16816(s[2 * bi + 1], ah, bl1);
                mma16816(s[2 * bi + 1], al, bh1);
            }
        }

        // ---- scale + causal mask + row max ----
        float rm0 = -1e30f, rm1 = -1e30f;
        #pragma unroll
        for (int j = 0; j < 8; j++) {
            int c = k0 + j * 8 + (lane & 3) * 2;
            s[j][0] = (c     <= gr0) ? s[j][0] * scale : -1e30f;
            s[j][1] = (c + 1 <= gr0) ? s[j][1] * scale : -1e30f;
            s[j][2] = (c     <= gr1) ? s[j][2] * scale : -1e30f;
            s[j][3] = (c + 1 <= gr1) ? s[j][3] * scale : -1e30f;
            rm0 = fmaxf(rm0, fmaxf(s[j][0], s[j][1]));
            rm1 = fmaxf(rm1, fmaxf(s[j][2], s[j][3]));
        }
        rm0 = fmaxf(rm0, __shfl_xor_sync(0xffffffffu, rm0, 1));
        rm0 = fmaxf(rm0, __shfl_xor_sync(0xffffffffu, rm0, 2));
        rm1 = fmaxf(rm1, __shfl_xor_sync(0xffffffffu, rm1, 1));
        rm1 = fmaxf(rm1, __shfl_xor_sync(0xffffffffu, rm1, 2));

        float mn0 = fmaxf(m0, rm0), mn1 = fmaxf(m1, rm1);
        float a0 = __expf(m0 - mn0), a1 = __expf(m1 - mn1);
        m0 = mn0; m1 = mn1;

        // ---- exp + pack P hi/lo into A fragments ----
        uint32_t ph[4][4], pl[4][4];
        float ps0 = 0.f, ps1 = 0.f;
        #pragma unroll
        for (int j = 0; j < 8; j++) {
            float p0 = __expf(s[j][0] - mn0);
            float p1 = __expf(s[j][1] - mn0);
            float p2 = __expf(s[j][2] - mn1);
            float p3 = __expf(s[j][3] - mn1);
            ps0 += p0 + p1;
            ps1 += p2 + p3;
            uint32_t hA = pack_bf16x2(p0, p1);
            uint32_t hB = pack_bf16x2(p2, p3);
            float h0 = __bfloat162float(__float2bfloat16(p0));
            float h1 = __bfloat162float(__float2bfloat16(p1));
            float h2 = __bfloat162float(__float2bfloat16(p2));
            float h3 = __bfloat162float(__float2bfloat16(p3));
            uint32_t lA = pack_bf16x2(p0 - h0, p1 - h1);
            uint32_t lB = pack_bf16x2(p2 - h2, p3 - h3);
            int kc = j >> 1;
            if ((j & 1) == 0) {
                ph[kc][0] = hA; ph[kc][1] = hB;
                pl[kc][0] = lA; pl[kc][1] = lB;
            } else {
                ph[kc][2] = hA; ph[kc][3] = hB;
                pl[kc][2] = lA; pl[kc][3] = lB;
            }
        }
        l0 = l0 * a0 + ps0;
        l1 = l1 * a1 + ps1;

        // rescale O accumulators
        #pragma unroll
        for (int j = 0; j < 16; j++) {
            o[j][0] *= a0; o[j][1] *= a0;
            o[j][2] *= a1; o[j][3] *= a1;
        }

        // ---- O += P V (bf16x3) ----
        #pragma unroll
        for (int kc = 0; kc < 4; kc++) {
            #pragma unroll
            for (int vi = 0; vi < 8; vi++) {
                uint32_t va = (kc * 16 + lr) * APITCH + vi * 32 + lch;
                uint32_t t0, t1, t2, t3, u0, u1, u2, u3;
                ldsm4t(t0, t1, t2, t3, sVh + va);
                ldsm4t(u0, u1, u2, u3, sVl + va);
                uint32_t bh0[2] = {t0, t1}, bh1[2] = {t2, t3};
                uint32_t bl0[2] = {u0, u1}, bl1[2] = {u2, u3};
                mma16816(o[2 * vi],     ph[kc], bh0);
                mma16816(o[2 * vi],     ph[kc], bl0);
                mma16816(o[2 * vi],     pl[kc], bh0);
                mma16816(o[2 * vi + 1], ph[kc], bh1);
                mma16816(o[2 * vi + 1], ph[kc], bl1);
                mma16816(o[2 * vi + 1], pl[kc], bh1);
            }
        }
    }

    // reduce l across the quad, normalize, store
    l0 += __shfl_xor_sync(0xffffffffu, l0, 1);
    l0 += __shfl_xor_sync(0xffffffffu, l0, 2);
    l1 += __shfl_xor_sync(0xffffffffu, l1, 1);
    l1 += __shfl_xor_sync(0xffffffffu, l1, 2);
    float inv0 = 1.f / l0, inv1 = 1.f / l1;

    #pragma unroll
    for (int j = 0; j < 16; j++) {
        int c = n * HD + j * 8 + (lane & 3) * 2;
        float2 v0 = { o[j][0] * inv0, o[j][1] * inv0 };
        float2 v1 = { o[j][2] * inv1, o[j][3] * inv1 };
        *(float2*)(ob + (size_t)gr0 * QW + c) = v0;
        *(float2*)(ob + (size_t)gr1 * QW + c) = v1;
    }
}

// ---------------------------------------------------------------------------
// Launch
//   inputs: 0:x 1:attn_mask 2:sin 3:cos 4:wq 5:wk 6:wv 7:wo 8:q_bias 9:k_bias 10:v_bias
// ---------------------------------------------------------------------------
extern "C" void kernel_launch(void* const* d_in, const int* in_sizes, int n_in,
                              void* d_out, int out_size)
{
    const float* x      = (const float*)d_in[0];
    const float* sinT   = (const float*)d_in[2];
    const float* cosT   = (const float*)d_in[3];
    const float* wq     = (const float*)d_in[4];
    const float* wk     = (const float*)d_in[5];
    const float* wv     = (const float*)d_in[6];
    const float* wo     = (const float*)d_in[7];
    const float* q_bias = (const float*)d_in[8];
    const float* k_bias = (const float*)d_in[9];
    const float* v_bias = (const float*)d_in[10];
    float* out = (float*)d_out;

    float *qp, *kp, *vp, *aop;
    cudaGetSymbolAddress((void**)&qp,  g_q);
    cudaGetSymbolAddress((void**)&kp,  g_k);
    cudaGetSymbolAddress((void**)&vp,  g_v);
    cudaGetSymbolAddress((void**)&aop, g_ao);

    __nv_bfloat16 *xhi, *xlo, *aohi, *aolo;
    __nv_bfloat16 *qhi, *qlo, *khi, *klo, *vhi, *vlo;
    __nv_bfloat16 *wqh, *wql, *wkh, *wkl, *wvh, *wvl, *woh, *wol;
    cudaGetSymbolAddress((void**)&xhi,  g_xhi);
    cudaGetSymbolAddress((void**)&xlo,  g_xlo);
    cudaGetSymbolAddress((void**)&aohi, g_aohi);
    cudaGetSymbolAddress((void**)&aolo, g_aolo);
    cudaGetSymbolAddress((void**)&qhi,  g_qhi);
    cudaGetSymbolAddress((void**)&qlo,  g_qlo);
    cudaGetSymbolAddress((void**)&khi,  g_khi);
    cudaGetSymbolAddress((void**)&klo,  g_klo);
    cudaGetSymbolAddress((void**)&vhi,  g_vhi);
    cudaGetSymbolAddress((void**)&vlo,  g_vlo);
    cudaGetSymbolAddress((void**)&wqh,  g_wqT_hi);
    cudaGetSymbolAddress((void**)&wql,  g_wqT_lo);
    cudaGetSymbolAddress((void**)&wkh,  g_wkT_hi);
    cudaGetSymbolAddress((void**)&wkl,  g_wkT_lo);
    cudaGetSymbolAddress((void**)&wvh,  g_wvT_hi);
    cudaGetSymbolAddress((void**)&wvl,  g_wvT_lo);
    cudaGetSymbolAddress((void**)&woh,  g_woT_hi);
    cudaGetSymbolAddress((void**)&wol,  g_woT_lo);

    cudaFuncSetAttribute(gemm_bf16x3,
                         cudaFuncAttributeMaxDynamicSharedMemorySize, GSMEM);
    cudaFuncSetAttribute(attn_mma,
                         cudaFuncAttributeMaxDynamicSharedMemorySize, ASMEM);

    // 1) operand prep: split x; transpose+split weights
    {
        int n4 = TT * DD / 4;
        split_kernel<<<(n4 + 255) / 256, 256>>>(x, xhi, xlo, n4);

        dim3 blk(32, 8);
        transpose_split_kernel<<<dim3(QW / 32, DD / 32),  blk>>>(wq, wqh, wql, DD, QW);
        transpose_split_kernel<<<dim3(KVW / 32, DD / 32), blk>>>(wk, wkh, wkl, DD, KVW);
        transpose_split_kernel<<<dim3(KVW / 32, DD / 32), blk>>>(wv, wvh, wvl, DD, KVW);
        transpose_split_kernel<<<dim3(DD / 32, QW / 32),  blk>>>(wo, woh, wol, QW, DD);
    }

    // 2) QKV projections (tensor cores)
    gemm_bf16x3<<<dim3(QW / 128,  TT / 128), 256, GSMEM>>>(xhi, xlo, wqh, wql, q_bias, qp, DD, QW);
    gemm_bf16x3<<<dim3(KVW / 128, TT / 128), 256, GSMEM>>>(xhi, xlo, wkh, wkl, k_bias, kp, DD, KVW);
    gemm_bf16x3<<<dim3(KVW / 128, TT / 128), 256, GSMEM>>>(xhi, xlo, wvh, wvl, v_bias, vp, DD, KVW);

    // 3) RoPE fused with bf16 hi/lo split; V split
    {
        int totq = TT * NH * (HD / 2);
        rope_split_kernel<<<(totq + 255) / 256, 256>>>(qp, sinT, cosT, qhi, qlo, NH);
        int totk = TT * KVH * (HD / 2);
        rope_split_kernel<<<(totk + 255) / 256, 256>>>(kp, sinT, cosT, khi, klo, KVH);
        int n4 = TT * KVW / 4;
        split_kernel<<<(n4 + 255) / 256, 256>>>(vp, vhi, vlo, n4);
    }

    // 4) Attention (tensor cores, bf16x3)
    {
        dim3 grid(TT / 64, NH);
        attn_mma<<<grid, 128, ASMEM>>>(qhi, qlo, khi, klo, vhi, vlo, aop);
    }

    // 5) Output projection (tensor cores)
    {
        int n4 = TT * QW / 4;
        split_kernel<<<(n4 + 255) / 256, 256>>>(aop, aohi, aolo, n4);
        gemm_bf16x3<<<dim3(QW / 128, TT / 128), 256, GSMEM>>>(aohi, aolo, woh, wol, nullptr, out, QW, QW);
    }
}